// round 14
// baseline (speedup 1.0000x reference)
#include <cuda_runtime.h>
#include <cstdint>
#include <math.h>

#define TT 4096
#define HH 2048
#define EE 32
#define II 1024
#define TOPK 8
#define MAXPAIRS (TT * TOPK)

// ---------------- device scratch (BSS, allocation-free) ----------------
__device__ int   g_count[EE];
__device__ int   g_cursor[EE];
__device__ int   g_off[EE + 1];
__device__ int   g_topk_e[MAXPAIRS];
__device__ float g_topk_w[MAXPAIRS];
__device__ int   g_pair_tok[MAXPAIRS];
__device__ float g_pair_w[MAXPAIRS];
__device__ int   g_slot[MAXPAIRS];
__device__ float g_xr [(size_t)TT * HH];           // tf32-rounded x
__device__ float g_wgr[(size_t)EE * HH * II];      // tf32-rounded weights
__device__ float g_wur[(size_t)EE * HH * II];
__device__ float g_wdr[(size_t)EE * II * HH];
__device__ float g_h  [(size_t)MAXPAIRS * II];     // intermediate (tf32-rounded)
__device__ float g_y  [(size_t)MAXPAIRS * HH];     // weighted expert outputs

// ---------------- helpers ----------------
__device__ __forceinline__ uint32_t smem_u32(const void* p) {
    uint32_t a;
    asm("{ .reg .u64 t; cvta.to.shared.u64 t, %1; cvt.u32.u64 %0, t; }" : "=r"(a) : "l"(p));
    return a;
}
__device__ __forceinline__ float tf32r(float v) {
    uint32_t u;
    asm("cvt.rna.tf32.f32 %0, %1;" : "=r"(u) : "f"(v));
    return __uint_as_float(u);
}
__device__ __forceinline__ float4 tf32r4(float4 v) {
    v.x = tf32r(v.x); v.y = tf32r(v.y); v.z = tf32r(v.z); v.w = tf32r(v.w);
    return v;
}
__device__ __forceinline__ void mma_t32(float* c, const uint32_t* a, const uint32_t* b) {
    asm volatile(
        "mma.sync.aligned.m16n8k8.row.col.f32.tf32.tf32.f32 "
        "{%0,%1,%2,%3}, {%4,%5,%6,%7}, {%8,%9}, {%0,%1,%2,%3};"
        : "+f"(c[0]), "+f"(c[1]), "+f"(c[2]), "+f"(c[3])
        : "r"(a[0]), "r"(a[1]), "r"(a[2]), "r"(a[3]), "r"(b[0]), "r"(b[1]));
}
__device__ __forceinline__ void cp16(uint32_t dst, const void* src) {
    asm volatile("cp.async.cg.shared.global [%0], [%1], 16;" :: "r"(dst), "l"(src));
}
#define CP_COMMIT() asm volatile("cp.async.commit_group;" ::: "memory")
#define CP_WAIT2()  asm volatile("cp.async.wait_group 2;" ::: "memory")

// ---------------- init ----------------
__global__ void init_kernel() {
    int i = threadIdx.x;
    if (i < EE) { g_count[i] = 0; g_cursor[i] = 0; }
}

// ---------------- round to tf32 (prep, weights only) ----------------
__global__ void round_kernel(const float4* __restrict__ src, float4* __restrict__ dst, int n4) {
    int i = blockIdx.x * blockDim.x + threadIdx.x;
    if (i < n4) dst[i] = tf32r4(src[i]);
}

// ---------------- router (also writes tf32-rounded x) ----------------
__global__ void router_kernel(const float* __restrict__ x,
                              const float* __restrict__ gate_w,
                              float* __restrict__ out, int write_ids) {
    int t = blockIdx.x;
    int tid = threadIdx.x;           // 128
    int e = tid >> 2, p = tid & 3;
    const float* xr = x + (size_t)t * HH;
    float s = 0.f;
    for (int h = p; h < HH; h += 4)
        s += xr[h] * gate_w[(size_t)h * EE + e];
    // fused: write tf32-rounded x row (L1-resident)
    for (int h = tid; h < HH; h += 128)
        g_xr[(size_t)t * HH + h] = tf32r(xr[h]);
    __shared__ float part[EE][4];
    part[e][p] = s;
    __syncthreads();
    __shared__ float sc[EE];
    if (tid < EE)
        sc[tid] = part[tid][0] + part[tid][1] + part[tid][2] + part[tid][3];
    __syncthreads();
    if (tid == 0) {
        float mx = sc[0];
        #pragma unroll
        for (int i = 1; i < EE; i++) mx = fmaxf(mx, sc[i]);
        float sum = 0.f;
        for (int i = 0; i < EE; i++) { sc[i] = expf(sc[i] - mx); sum += sc[i]; }
        float inv = 1.f / sum;
        for (int i = 0; i < EE; i++) sc[i] *= inv;
        int ids[TOPK]; float ws[TOPK];
        unsigned used = 0u; float wsum = 0.f;
        for (int k = 0; k < TOPK; k++) {
            int best = 0; float bv = -1.f;
            for (int i = 0; i < EE; i++)
                if (!((used >> i) & 1u) && sc[i] > bv) { bv = sc[i]; best = i; }
            used |= (1u << best); ids[k] = best; ws[k] = bv; wsum += bv;
        }
        float invw = 1.f / wsum;
        for (int k = 0; k < TOPK; k++) {
            g_topk_e[t * TOPK + k] = ids[k];
            g_topk_w[t * TOPK + k] = ws[k] * invw;
            atomicAdd(&g_count[ids[k]], 1);
            if (write_ids)
                out[(size_t)TT * HH + (size_t)t * TOPK + k] = (float)ids[k];
        }
    }
}

__global__ void prefix_kernel() {
    if (threadIdx.x == 0) {
        int acc = 0;
        for (int e = 0; e < EE; e++) { g_off[e] = acc; acc += g_count[e]; }
        g_off[EE] = acc;
    }
}

__global__ void scatter_kernel() {
    int idx = blockIdx.x * blockDim.x + threadIdx.x;
    if (idx >= TT * TOPK) return;
    int e = g_topk_e[idx];
    int pos = atomicAdd(&g_cursor[e], 1);
    int slot = g_off[e] + pos;
    g_pair_tok[slot] = idx / TOPK;
    g_pair_w[slot]   = g_topk_w[idx];
    g_slot[idx]      = slot;
}

// ================= GEMM1: h = silu(X@Wg) * (X@Wu) =================
// BM=128, BN=128, BK=32. 8 warps (2Mx4N), warp tile 64x32 dual (gate+up).
// 4-stage cp.async. Grid: (N-blocks fastest, M-blocks, experts) for L2 reuse of A.
#define G1_STAGE_F 13312
#define G1_SMEM (4 * G1_STAGE_F * 4 + 512)
__global__ __launch_bounds__(256, 1) void moe_gemm1() {
    const int e   = blockIdx.z;
    const int cnt = g_count[e];
    const int m0  = blockIdx.y * 128;
    if (m0 >= cnt) return;
    const int n0  = blockIdx.x * 128;
    const int off = g_off[e];

    extern __shared__ float sm[];
    int* toks = (int*)(sm + 4 * G1_STAGE_F);
    const int tid = threadIdx.x;
    for (int r = tid; r < 128; r += 256)
        toks[r] = (m0 + r < cnt) ? g_pair_tok[off + m0 + r] : 0;
    __syncthreads();

    const uint32_t sb = smem_u32(sm);
    const int ar = tid >> 3, ac = (tid & 7);
    const float* aptr[4];
    #pragma unroll
    for (int j = 0; j < 4; j++)
        aptr[j] = g_xr + (size_t)toks[ar + 32 * j] * HH + ac * 4;
    const int br = tid >> 5, bc = (tid & 31);
    const float* gbase = g_wgr + (size_t)e * HH * II + n0 + bc * 4;
    const float* ubase = g_wur + (size_t)e * HH * II + n0 + bc * 4;

    const int lane = tid & 31, wid = tid >> 5;
    const int gid = lane >> 2, tig = lane & 3;
    const int wm = (wid >> 2) * 64, wn = (wid & 3) * 32;

    float cg[4][4][4], cu[4][4][4];
    #pragma unroll
    for (int i = 0; i < 4; i++)
        #pragma unroll
        for (int j = 0; j < 4; j++)
            #pragma unroll
            for (int q = 0; q < 4; q++) { cg[i][j][q] = 0.f; cu[i][j][q] = 0.f; }

    const int KT = HH / 32;
    #pragma unroll 1
    for (int kt = -3; kt < KT; kt++) {
        const int ft = kt + 3;
        if (ft < KT) {
            const int s = ft & 3;
            const int k0 = ft * 32;
            const uint32_t a_s = sb + s * (G1_STAGE_F * 4);
            #pragma unroll
            for (int j = 0; j < 4; j++)
                cp16(a_s + (ar + 32 * j) * 144 + ac * 16, aptr[j] + k0);
            const uint32_t g_s = a_s + 4608 * 4;
            const uint32_t u_s = g_s + 4352 * 4;
            #pragma unroll
            for (int j = 0; j < 4; j++) {
                cp16(g_s + (br + 8 * j) * 544 + bc * 16, gbase + (size_t)(k0 + br + 8 * j) * II);
                cp16(u_s + (br + 8 * j) * 544 + bc * 16, ubase + (size_t)(k0 + br + 8 * j) * II);
            }
        }
        CP_COMMIT();
        if (kt < 0) continue;
        CP_WAIT2();
        __syncthreads();
        const float* A = sm + (kt & 3) * G1_STAGE_F;
        const float* G = A + 4608;
        const float* U = G + 4352;
        #pragma unroll
        for (int ks = 0; ks < 4; ks++) {
            const int kb = ks * 8;
            uint32_t af[4][4], bg[4][2], bu[4][2];
            #pragma unroll
            for (int mi = 0; mi < 4; mi++) {
                const int r = wm + mi * 16 + gid;
                af[mi][0] = __float_as_uint(A[r * 36 + kb + tig]);
                af[mi][1] = __float_as_uint(A[(r + 8) * 36 + kb + tig]);
                af[mi][2] = __float_as_uint(A[r * 36 + kb + tig + 4]);
                af[mi][3] = __float_as_uint(A[(r + 8) * 36 + kb + tig + 4]);
            }
            #pragma unroll
            for (int ni = 0; ni < 4; ni++) {
                const int c = wn + ni * 8 + gid;
                bg[ni][0] = __float_as_uint(G[(kb + tig) * 136 + c]);
                bg[ni][1] = __float_as_uint(G[(kb + tig + 4) * 136 + c]);
                bu[ni][0] = __float_as_uint(U[(kb + tig) * 136 + c]);
                bu[ni][1] = __float_as_uint(U[(kb + tig + 4) * 136 + c]);
            }
            #pragma unroll
            for (int mi = 0; mi < 4; mi++)
                #pragma unroll
                for (int ni = 0; ni < 4; ni++) {
                    mma_t32(cg[mi][ni], af[mi], bg[ni]);
                    mma_t32(cu[mi][ni], af[mi], bu[ni]);
                }
        }
        __syncthreads();
    }
    // epilogue: silu(g)*u, tf32-round, store
    #pragma unroll
    for (int mi = 0; mi < 4; mi++) {
        #pragma unroll
        for (int half = 0; half < 2; half++) {
            const int m = m0 + wm + mi * 16 + gid + half * 8;
            if (m < cnt) {
                float* hrow = g_h + (size_t)(off + m) * II + n0 + wn;
                #pragma unroll
                for (int ni = 0; ni < 4; ni++) {
                    float g0 = cg[mi][ni][half * 2], g1 = cg[mi][ni][half * 2 + 1];
                    float u0 = cu[mi][ni][half * 2], u1 = cu[mi][ni][half * 2 + 1];
                    float2 o;
                    o.x = tf32r(g0 / (1.f + __expf(-g0)) * u0);
                    o.y = tf32r(g1 / (1.f + __expf(-g1)) * u1);
                    *(float2*)(hrow + ni * 8 + tig * 2) = o;
                }
            }
        }
    }
}

// ================= GEMM2: y[slot] = w * (h @ Wd) =================
// BM=128, BN=256, BK=32. 8 warps (2Mx4N), warp tile 64x64. 4-stage cp.async.
// Grid: (N-blocks fastest, M-blocks, experts).
#define G2_STAGE_F 13056
#define G2_SMEM (4 * G2_STAGE_F * 4 + 512)
__global__ __launch_bounds__(256, 1) void moe_gemm2() {
    const int e   = blockIdx.z;
    const int cnt = g_count[e];
    const int m0  = blockIdx.y * 128;
    if (m0 >= cnt) return;
    const int n0  = blockIdx.x * 256;
    const int off = g_off[e];

    extern __shared__ float sm[];
    float* wts = sm + 4 * G2_STAGE_F;
    const int tid = threadIdx.x;
    for (int r = tid; r < 128; r += 256)
        wts[r] = (m0 + r < cnt) ? g_pair_w[off + m0 + r] : 0.f;
    __syncthreads();

    const uint32_t sb = smem_u32(sm);
    const int ar = tid >> 3, ac = (tid & 7);
    const float* aptr[4];
    #pragma unroll
    for (int j = 0; j < 4; j++) {
        int row = m0 + ar + 32 * j;
        int slot = (row < cnt) ? (off + row) : off;
        aptr[j] = g_h + (size_t)slot * II + ac * 4;
    }
    const int br = tid >> 6, bc = (tid & 63);
    const float* bbase = g_wdr + (size_t)e * II * HH + n0 + bc * 4;

    const int lane = tid & 31, wid = tid >> 5;
    const int gid = lane >> 2, tig = lane & 3;
    const int wm = (wid >> 2) * 64, wn = (wid & 3) * 64;

    float c[4][8][4];
    #pragma unroll
    for (int i = 0; i < 4; i++)
        #pragma unroll
        for (int j = 0; j < 8; j++)
            #pragma unroll
            for (int q = 0; q < 4; q++) c[i][j][q] = 0.f;

    const int KT = II / 32;
    #pragma unroll 1
    for (int kt = -3; kt < KT; kt++) {
        const int ft = kt + 3;
        if (ft < KT) {
            const int s = ft & 3;
            const int k0 = ft * 32;
            const uint32_t a_s = sb + s * (G2_STAGE_F * 4);
            #pragma unroll
            for (int j = 0; j < 4; j++)
                cp16(a_s + (ar + 32 * j) * 144 + ac * 16, aptr[j] + k0);
            const uint32_t b_s = a_s + 4608 * 4;
            #pragma unroll
            for (int j = 0; j < 8; j++)
                cp16(b_s + (br + 4 * j) * 1056 + bc * 16, bbase + (size_t)(k0 + br + 4 * j) * HH);
        }
        CP_COMMIT();
        if (kt < 0) continue;
        CP_WAIT2();
        __syncthreads();
        const float* A = sm + (kt & 3) * G2_STAGE_F;
        const float* B = A + 4608;
        #pragma unroll
        for (int ks = 0; ks < 4; ks++) {
            const int kb = ks * 8;
            uint32_t af[4][4], bf[8][2];
            #pragma unroll
            for (int mi = 0; mi < 4; mi++) {
                const int r = wm + mi * 16 + gid;
                af[mi][0] = __float_as_uint(A[r * 36 + kb + tig]);
                af[mi][1] = __float_as_uint(A[(r + 8) * 36 + kb + tig]);
                af[mi][2] = __float_as_uint(A[r * 36 + kb + tig + 4]);
                af[mi][3] = __float_as_uint(A[(r + 8) * 36 + kb + tig + 4]);
            }
            #pragma unroll
            for (int ni = 0; ni < 8; ni++) {
                const int cc = wn + ni * 8 + gid;
                bf[ni][0] = __float_as_uint(B[(kb + tig) * 264 + cc]);
                bf[ni][1] = __float_as_uint(B[(kb + tig + 4) * 264 + cc]);
            }
            #pragma unroll
            for (int mi = 0; mi < 4; mi++)
                #pragma unroll
                for (int ni = 0; ni < 8; ni++)
                    mma_t32(c[mi][ni], af[mi], bf[ni]);
        }
        __syncthreads();
    }
    // epilogue: weighted store into g_y
    #pragma unroll
    for (int mi = 0; mi < 4; mi++) {
        #pragma unroll
        for (int half = 0; half < 2; half++) {
            const int ml = wm + mi * 16 + gid + half * 8;
            const int m  = m0 + ml;
            if (m < cnt) {
                const float w = wts[ml];
                float* yrow = g_y + (size_t)(off + m) * HH + n0 + wn;
                #pragma unroll
                for (int ni = 0; ni < 8; ni++) {
                    float2 o;
                    o.x = w * c[mi][ni][half * 2];
                    o.y = w * c[mi][ni][half * 2 + 1];
                    *(float2*)(yrow + ni * 8 + tig * 2) = o;
                }
            }
        }
    }
}

// ---------------- combine: out[t] = sum_k g_y[slot(t,k)] ----------------
__global__ void combine_kernel(float* __restrict__ out) {
    const int t = blockIdx.x;
    const int tid = threadIdx.x;   // 256
    __shared__ int s8[TOPK];
    if (tid < TOPK) s8[tid] = g_slot[t * TOPK + tid];
    __syncthreads();
    #pragma unroll
    for (int rep = 0; rep < 2; rep++) {
        const int cc = (tid + rep * 256) * 4;
        float4 acc = make_float4(0.f, 0.f, 0.f, 0.f);
        #pragma unroll
        for (int k = 0; k < TOPK; k++) {
            const float4 v = *(const float4*)(g_y + (size_t)s8[k] * HH + cc);
            acc.x += v.x; acc.y += v.y; acc.z += v.z; acc.w += v.w;
        }
        *(float4*)(out + (size_t)t * HH + cc) = acc;
    }
}

// ---------------- launch ----------------
extern "C" void kernel_launch(void* const* d_in, const int* in_sizes, int n_in,
                              void* d_out, int out_size) {
    const float* x      = (const float*)d_in[0];
    const float* gate_w = (const float*)d_in[1];
    const float* w_gate = (const float*)d_in[2];
    const float* w_up   = (const float*)d_in[3];
    const float* w_down = (const float*)d_in[4];
    float* out = (float*)d_out;

    cudaFuncSetAttribute((const void*)moe_gemm1,
                         cudaFuncAttributeMaxDynamicSharedMemorySize, G1_SMEM);
    cudaFuncSetAttribute((const void*)moe_gemm2,
                         cudaFuncAttributeMaxDynamicSharedMemorySize, G2_SMEM);

    init_kernel<<<1, 32>>>();

    int write_ids = (out_size >= TT * HH + TT * TOPK) ? 1 : 0;
    router_kernel<<<TT, 128>>>(x, gate_w, out, write_ids);
    prefix_kernel<<<1, 32>>>();
    scatter_kernel<<<(TT * TOPK + 255) / 256, 256>>>();

    // tf32 pre-rounding (weights only; x folded into router)
    {
        float* wg = nullptr; float* wu = nullptr; float* wd = nullptr;
        cudaGetSymbolAddress((void**)&wg, g_wgr);
        cudaGetSymbolAddress((void**)&wu, g_wur);
        cudaGetSymbolAddress((void**)&wd, g_wdr);
        int nw = (int)((size_t)EE * HH * II / 4);
        round_kernel<<<(nw + 255) / 256, 256>>>((const float4*)w_gate, (float4*)wg, nw);
        round_kernel<<<(nw + 255) / 256, 256>>>((const float4*)w_up,   (float4*)wu, nw);
        round_kernel<<<(nw + 255) / 256, 256>>>((const float4*)w_down, (float4*)wd, nw);
    }

    // N-blocks fastest -> consecutive CTAs share the A tile; B stays hot in L2.
    moe_gemm1<<<dim3(II / 128, 32, EE), 256, G1_SMEM>>>();
    moe_gemm2<<<dim3(HH / 256, 32, EE), 256, G2_SMEM>>>();
    combine_kernel<<<TT, 256>>>(out);
}